// round 13
// baseline (speedup 1.0000x reference)
#include <cuda_runtime.h>

// Problem constants (match reference)
#define NB     4
#define HH     512
#define WW     512
#define KK     4
#define FMAX   200000
#define SIGMA  1e-4f
#define GAMMA  1e-4f
#define EPSV   1e-10f
#define ZNEAR  1.0f
#define ZFAR   100.0f

#define NPIX (NB * HH * WW)   // 1,048,576 == 4096 * 256 exactly
#define NBLK (NPIX / 256)     // 4096

// Producer blocks: must all fit in wave 1. launch_bounds(256,5) -> 5 CTA/SM
// -> wave 1 = 148*5 = 740 resident CTAs >= 512 producers.
#define PRE_BLOCKS    512
#define FACES_PER_BLK 391     // 512*391 = 200192 >= 200000

// 1/SIGMA and 1/GAMMA are exactly representable (10000.0f) -> mul == div.
#define INV_SG 10000.0f

// Weight cutoff: exp((zi-zmax)*1e4) < e^-40 ~ 4e-18 is < 1e-10 relative to the
// dominant weight (>= ~1e-7); the fp32 reference itself underflows to 0 below
// e^-87. Skipping these fragments skips their gather entirely.
#define Z_CUT  (40.0f / INV_SG)   // 0.004

// Packed per-face record: 32 bytes = ONE 32B L2 sector, loaded with a single
// 256-bit LDG.  a = (n0x,n0y,n0z,n1x), b = (n1y,n1z,n2x,n2y); the 32 bits of
// n2z are hidden in the low 4 mantissa bits of the 8 stored floats (nibble i
// in component i). n2z decode is bit-exact; carriers perturbed <=15 ulp.
struct __align__(32) FaceRec { float4 a, b; };
__device__ FaceRec g_facerec[FMAX];

// Producer-done counter + self-reset arrival counter (stateless across
// launches: last block out restores both to 0).
__device__ int g_done;
__device__ int g_arrive;

__device__ __forceinline__ unsigned fb(float v) { return __float_as_uint(v); }

// 256-bit global load (sm_100+). NOT .nc: records are produced in this launch.
__device__ __forceinline__ void ldg256(const FaceRec* p, float4& a, float4& b) {
    asm volatile("ld.global.v8.f32 {%0,%1,%2,%3,%4,%5,%6,%7}, [%8];"
                 : "=f"(a.x), "=f"(a.y), "=f"(a.z), "=f"(a.w),
                   "=f"(b.x), "=f"(b.y), "=f"(b.z), "=f"(b.w)
                 : "l"(p));
}

// Branchless gather of a 12B float3 at float-offset 3v using TWO aligned
// float2 loads (off = 3v - (v&1) is always even; both halves 8B-aligned and
// in-bounds for V=100000).
__device__ __forceinline__ float3 load_vn(const float* __restrict__ vn, int v) {
    const int off = 3 * v - (v & 1);
    const float2 A = __ldg((const float2*)vn + (off >> 1));
    const float2 B = __ldg((const float2*)vn + (off >> 1) + 1);
    const bool odd = (v & 1);
    float3 r;
    r.x = odd ? A.y : A.x;
    r.y = odd ? B.x : A.y;
    r.z = odd ? B.y : B.x;
    return r;
}

__device__ __forceinline__ void build_one_record(
    const float* __restrict__ vertex_normals,
    const int*   __restrict__ faces, int f)
{
    const int v0 = __ldg(faces + 3 * f + 0);
    const int v1 = __ldg(faces + 3 * f + 1);
    const int v2 = __ldg(faces + 3 * f + 2);
    const float3 n0 = load_vn(vertex_normals, v0);
    const float3 n1 = load_vn(vertex_normals, v1);
    const float3 n2 = load_vn(vertex_normals, v2);

    float c[8] = {n0.x, n0.y, n0.z, n1.x, n1.y, n1.z, n2.x, n2.y};
    const unsigned u = __float_as_uint(n2.z);
    #pragma unroll
    for (int i = 0; i < 8; i++) {
        unsigned bits = (__float_as_uint(c[i]) & ~0xFu) | ((u >> (4 * i)) & 0xFu);
        c[i] = __uint_as_float(bits);
    }

    FaceRec r;
    r.a = make_float4(c[0], c[1], c[2], c[3]);
    r.b = make_float4(c[4], c[5], c[6], c[7]);
    g_facerec[f] = r;
}

__global__ __launch_bounds__(256, 5) void fused_normal_shader(
    const float* __restrict__ vertex_normals,   // [V,3]
    const int*   __restrict__ faces,            // [F,3]
    const float* __restrict__ bary,             // [N,H,W,K,3]
    const float* __restrict__ dists,            // [N,H,W,K]
    const float* __restrict__ zbuf,             // [N,H,W,K]
    const int*   __restrict__ pix_to_face,      // [N,H,W,K]
    float*       __restrict__ out,              // [N,H,W,3]
    int F)
{
    __shared__ float so[256 * 3];
    const int tid = threadIdx.x;
    const int bid = blockIdx.x;
    const int p = bid * 256 + tid;              // grid covers NPIX exactly

    // ============ A. producer blocks build their face-record slice ========
    if (bid < PRE_BLOCKS) {
        const int fbeg = bid * FACES_PER_BLK;
        const int fend = min(fbeg + FACES_PER_BLK, F);
        for (int f = fbeg + tid; f < fend; f += 256)
            build_one_record(vertex_normals, faces, f);
        __syncthreads();
        if (tid == 0) {
            __threadfence();                    // release the records
            atomicAdd(&g_done, 1);
        }
    }

    // ============ B. phase 1 — independent of the records ================
    const int4   ptf = __ldg((const int4*)(pix_to_face) + p);
    const float4 zz  = __ldg((const float4*)(zbuf) + p);
    const float4 dd  = __ldg((const float4*)(dists) + p);
    const float4* bb = (const float4*)(bary + (size_t)p * 12);
    const float4 b0 = __ldg(bb + 0);
    const float4 b1 = __ldg(bb + 1);
    const float4 b2 = __ldg(bb + 2);

    const int   face[KK] = {ptf.x, ptf.y, ptf.z, ptf.w};
    const float zk[KK]   = {zz.x, zz.y, zz.z, zz.w};
    const float dk[KK]   = {dd.x, dd.y, dd.z, dd.w};
    const float bw[KK][3] = {
        {b0.x, b0.y, b0.z},
        {b0.w, b1.x, b1.y},
        {b1.z, b1.w, b2.x},
        {b2.y, b2.z, b2.w}
    };

    // zi MUST use exact IEEE div: 1 ulp amplifies ~1e4x in the exponent.
    float zinv[KK];
    float zmax = EPSV;
    #pragma unroll
    for (int k = 0; k < KK; k++) {
        const float zi = (face[k] >= 0) ? ((ZFAR - zk[k]) / (ZFAR - ZNEAR)) : 0.f;
        zinv[k] = zi;
        zmax = fmaxf(zmax, zi);
    }
    const float thr = zmax - Z_CUT;

    // Per-fragment softmax weights (0 for skipped fragments) — pre-wait.
    float wgt[KK];
    #pragma unroll
    for (int k = 0; k < KK; k++) {
        float w = 0.f;
        if (face[k] >= 0 && zinv[k] > thr) {
            // prob = sigmoid(-d/SIGMA)  (arg ~N(0,1); __expf err ~1e-6)
            const float pr = __fdividef(1.0f, 1.0f + __expf(dk[k] * INV_SG));
            w = pr * __expf((zinv[k] - zmax) * INV_SG);
        }
        wgt[k] = w;
    }

    // ============ C. wait for all producers (thread 0 spins, block syncs) =
    if (tid == 0) {
        int v;
        asm volatile("ld.acquire.gpu.global.b32 %0, [%1];"
                     : "=r"(v) : "l"(&g_done));
        while (v < PRE_BLOCKS) {
            __nanosleep(128);
            asm volatile("ld.acquire.gpu.global.b32 %0, [%1];"
                         : "=r"(v) : "l"(&g_done));
        }
    }
    __syncthreads();   // block-wide acquire

    // ============ D. phase 2 — gather surviving fragments + blend ========
    float accx = 0.f, accy = 0.f, accz = 0.f, wsum = 0.f;
    #pragma unroll
    for (int k = 0; k < KK; k++) {
        if (wgt[k] != 0.f) {
            float4 a, b;
            ldg256(g_facerec + face[k], a, b);
            // reconstruct n2z from the 8 stolen nibbles (bit-exact)
            unsigned u =  (fb(a.x) & 0xFu)
                       | ((fb(a.y) & 0xFu) << 4)
                       | ((fb(a.z) & 0xFu) << 8)
                       | ((fb(a.w) & 0xFu) << 12)
                       | ((fb(b.x) & 0xFu) << 16)
                       | ((fb(b.y) & 0xFu) << 20)
                       | ((fb(b.z) & 0xFu) << 24)
                       | ((fb(b.w) & 0xFu) << 28);
            const float n2z = __uint_as_float(u);
            const float w0 = bw[k][0], w1 = bw[k][1], w2 = bw[k][2];
            const float w  = wgt[k];
            wsum += w;
            accx += w * (w0 * a.x + w1 * a.w + w2 * b.z);
            accy += w * (w0 * a.y + w1 * b.x + w2 * b.w);
            accz += w * (w0 * a.z + w1 * b.y + w2 * n2z);
        }
    }

    const float delta  = fmaxf(__expf((EPSV - zmax) * INV_SG), EPSV);
    const float rdenom = __fdividef(1.0f, wsum + delta);

    // bg = (1,1,1)
    float rx = (accx + delta) * rdenom;
    float ry = (accy + delta) * rdenom;
    float rz = (accz + delta) * rdenom;

    const float n2 = rx * rx + ry * ry + rz * rz;
    const float inv = (n2 > 1e-24f) ? rsqrtf(n2) : 1e12f;
    rx *= inv; ry *= inv; rz *= inv;

    // ---- coalesced store via smem staging (3 STG.128 wavefronts/warp) ----
    so[3 * tid + 0] = rx;
    so[3 * tid + 1] = ry;
    so[3 * tid + 2] = rz;
    __syncthreads();
    if (tid < 192) {
        float4* ob = (float4*)(out + (size_t)bid * 768);
        const float4* sp = (const float4*)so;
        ob[tid] = sp[tid];
    }

    // ============ E. self-reset: last block out restores counters ========
    __syncthreads();
    if (tid == 0) {
        const int a = atomicAdd(&g_arrive, 1);
        if (a == NBLK - 1) {       // everyone (incl. all producers) is done
            g_done = 0;
            g_arrive = 0;
        }
    }
}

extern "C" void kernel_launch(void* const* d_in, const int* in_sizes, int n_in,
                              void* d_out, int out_size)
{
    // metadata order: verts, vertex_normals, bary_coords, dists, zbuf, faces, pix_to_face
    const float* vertex_normals = (const float*)d_in[1];
    const float* bary           = (const float*)d_in[2];
    const float* dists          = (const float*)d_in[3];
    const float* zbuf           = (const float*)d_in[4];
    const int*   faces          = (const int*)d_in[5];
    const int*   pix_to_face    = (const int*)d_in[6];
    float*       out            = (float*)d_out;

    const int F = in_sizes[5] / 3;   // 200000

    fused_normal_shader<<<NBLK, 256>>>(
        vertex_normals, faces, bary, dists, zbuf, pix_to_face, out, F);
}

// round 14
// speedup vs baseline: 1.1298x; 1.1298x over previous
#include <cuda_runtime.h>

// Problem constants (match reference)
#define NB     4
#define HH     512
#define WW     512
#define KK     4
#define FMAX   200000
#define SIGMA  1e-4f
#define GAMMA  1e-4f
#define EPSV   1e-10f
#define ZNEAR  1.0f
#define ZFAR   100.0f

#define NPIX (NB * HH * WW)   // 1,048,576 == 2048 * 512 exactly

// 1/SIGMA and 1/GAMMA are exactly representable (10000.0f) -> mul == div.
#define INV_SG 10000.0f

// Weight cutoff: exp((zi-zmax)*1e4) < e^-40 ~ 4e-18 is < 1e-10 relative to the
// dominant weight (>= ~1e-7); the fp32 reference itself underflows to 0 below
// e^-87. Skipping these fragments skips their gather entirely.
#define Z_CUT  (40.0f / INV_SG)   // 0.004

// Packed per-face record: 32 bytes = ONE 32B L2 sector, loaded with a single
// 256-bit LDG.  a = (n0x,n0y,n0z,n1x), b = (n1y,n1z,n2x,n2y); the 32 bits of
// n2z are hidden in the low 4 mantissa bits of the 8 stored floats (nibble i
// in component i). n2z decode is bit-exact; carriers perturbed <=15 ulp.
struct __align__(32) FaceRec { float4 a, b; };
__device__ FaceRec g_facerec[FMAX];

__device__ __forceinline__ unsigned fb(float v) { return __float_as_uint(v); }

// 256-bit global load (sm_100+): one instruction, one sector per lane.
__device__ __forceinline__ void ldg256(const FaceRec* p, float4& a, float4& b) {
    asm("ld.global.nc.v8.f32 {%0,%1,%2,%3,%4,%5,%6,%7}, [%8];"
        : "=f"(a.x), "=f"(a.y), "=f"(a.z), "=f"(a.w),
          "=f"(b.x), "=f"(b.y), "=f"(b.z), "=f"(b.w)
        : "l"(p));
}

// Branchless gather of a 12B float3 at float-offset 3v using TWO aligned
// float2 loads (off = 3v - (v&1) is always even; both halves 8B-aligned and
// in-bounds for V=100000).
__device__ __forceinline__ float3 load_vn(const float* __restrict__ vn, int v) {
    const int off = 3 * v - (v & 1);
    const float2 A = __ldg((const float2*)vn + (off >> 1));
    const float2 B = __ldg((const float2*)vn + (off >> 1) + 1);
    const bool odd = (v & 1);
    float3 r;
    r.x = odd ? A.y : A.x;
    r.y = odd ? B.x : A.y;
    r.z = odd ? B.y : B.x;
    return r;
}

__global__ __launch_bounds__(256) void build_face_records(
    const float* __restrict__ vertex_normals,   // [V,3]
    const int*   __restrict__ faces,            // [F,3]
    int F)
{
    // Let the dependent (main) kernel launch immediately; it only consumes
    // g_facerec after cudaGridDependencySynchronize().
    cudaTriggerProgrammaticLaunchCompletion();

    int f = blockIdx.x * blockDim.x + threadIdx.x;
    if (f >= F) return;
    const int v0 = __ldg(faces + 3 * f + 0);
    const int v1 = __ldg(faces + 3 * f + 1);
    const int v2 = __ldg(faces + 3 * f + 2);
    const float3 n0 = load_vn(vertex_normals, v0);
    const float3 n1 = load_vn(vertex_normals, v1);
    const float3 n2 = load_vn(vertex_normals, v2);

    float c[8] = {n0.x, n0.y, n0.z, n1.x, n1.y, n1.z, n2.x, n2.y};
    const unsigned u = __float_as_uint(n2.z);
    #pragma unroll
    for (int i = 0; i < 8; i++) {
        unsigned bits = (__float_as_uint(c[i]) & ~0xFu) | ((u >> (4 * i)) & 0xFu);
        c[i] = __uint_as_float(bits);
    }

    FaceRec r;
    r.a = make_float4(c[0], c[1], c[2], c[3]);
    r.b = make_float4(c[4], c[5], c[6], c[7]);
    g_facerec[f] = r;
}

// 2 pixels per thread: block covers 512 consecutive pixels.
__global__ __launch_bounds__(256) void normal_shader_kernel(
    const float* __restrict__ bary,             // [N,H,W,K,3]
    const float* __restrict__ dists,            // [N,H,W,K]
    const float* __restrict__ zbuf,             // [N,H,W,K]
    const int*   __restrict__ pix_to_face,      // [N,H,W,K]
    float*       __restrict__ out)              // [N,H,W,3]
{
    __shared__ float so[512 * 3];
    const int tid  = threadIdx.x;
    const int base = blockIdx.x * 512;          // grid covers NPIX exactly

    // State carried across the dependency sync (small on purpose).
    int   face[2][KK];
    float wgt[2][KK];
    float zmax[2];

    // ========== PHASE 1 — independent of g_facerec (overlaps prepass) =====
    #pragma unroll
    for (int h = 0; h < 2; h++) {
        const int p = base + h * 256 + tid;
        const int4   ptf = __ldg((const int4*)(pix_to_face) + p);
        const float4 zz  = __ldg((const float4*)(zbuf) + p);
        const float4 dd  = __ldg((const float4*)(dists) + p);

        const int   fc[KK] = {ptf.x, ptf.y, ptf.z, ptf.w};
        const float zk[KK] = {zz.x, zz.y, zz.z, zz.w};
        const float dk[KK] = {dd.x, dd.y, dd.z, dd.w};

        // zi MUST use exact IEEE div: 1 ulp amplifies ~1e4x in the exponent.
        float zinv[KK];
        float zm = EPSV;
        #pragma unroll
        for (int k = 0; k < KK; k++) {
            const float zi = (fc[k] >= 0) ? ((ZFAR - zk[k]) / (ZFAR - ZNEAR)) : 0.f;
            zinv[k] = zi;
            zm = fmaxf(zm, zi);
        }
        const float thr = zm - Z_CUT;

        #pragma unroll
        for (int k = 0; k < KK; k++) {
            float w = 0.f;
            if (fc[k] >= 0 && zinv[k] > thr) {
                // prob = sigmoid(-d/SIGMA)  (arg ~N(0,1); __expf err ~1e-6)
                const float pr = __fdividef(1.0f, 1.0f + __expf(dk[k] * INV_SG));
                w = pr * __expf((zinv[k] - zm) * INV_SG);
            }
            wgt[h][k]  = w;
            face[h][k] = fc[k];
        }
        zmax[h] = zm;
    }

    // ========== PHASE 2 — needs the face records ==========================
    cudaGridDependencySynchronize();

    #pragma unroll
    for (int h = 0; h < 2; h++) {
        const int p = base + h * 256 + tid;
        // bary loaded post-sync (coalesced; keeps it out of the live set
        // across the wait).
        const float4* bb = (const float4*)(bary + (size_t)p * 12);
        const float4 b0 = __ldg(bb + 0);
        const float4 b1 = __ldg(bb + 1);
        const float4 b2 = __ldg(bb + 2);
        const float bw[KK][3] = {
            {b0.x, b0.y, b0.z},
            {b0.w, b1.x, b1.y},
            {b1.z, b1.w, b2.x},
            {b2.y, b2.z, b2.w}
        };

        float accx = 0.f, accy = 0.f, accz = 0.f, wsum = 0.f;
        #pragma unroll
        for (int k = 0; k < KK; k++) {
            if (wgt[h][k] != 0.f) {
                float4 a, b;
                ldg256(g_facerec + face[h][k], a, b);
                // reconstruct n2z from the 8 stolen nibbles (bit-exact)
                unsigned u =  (fb(a.x) & 0xFu)
                           | ((fb(a.y) & 0xFu) << 4)
                           | ((fb(a.z) & 0xFu) << 8)
                           | ((fb(a.w) & 0xFu) << 12)
                           | ((fb(b.x) & 0xFu) << 16)
                           | ((fb(b.y) & 0xFu) << 20)
                           | ((fb(b.z) & 0xFu) << 24)
                           | ((fb(b.w) & 0xFu) << 28);
                const float n2z = __uint_as_float(u);
                const float w0 = bw[k][0], w1 = bw[k][1], w2 = bw[k][2];
                const float w  = wgt[h][k];
                wsum += w;
                accx += w * (w0 * a.x + w1 * a.w + w2 * b.z);
                accy += w * (w0 * a.y + w1 * b.x + w2 * b.w);
                accz += w * (w0 * a.z + w1 * b.y + w2 * n2z);
            }
        }

        const float delta  = fmaxf(__expf((EPSV - zmax[h]) * INV_SG), EPSV);
        const float rdenom = __fdividef(1.0f, wsum + delta);

        // bg = (1,1,1)
        float rx = (accx + delta) * rdenom;
        float ry = (accy + delta) * rdenom;
        float rz = (accz + delta) * rdenom;

        const float n2 = rx * rx + ry * ry + rz * rz;
        const float inv = (n2 > 1e-24f) ? rsqrtf(n2) : 1e12f;
        rx *= inv; ry *= inv; rz *= inv;

        const int s = h * 256 + tid;
        so[3 * s + 0] = rx;
        so[3 * s + 1] = ry;
        so[3 * s + 2] = rz;
    }

    // ---- coalesced store via smem staging (STG.128) ----
    __syncthreads();
    {
        float4* ob = (float4*)(out + (size_t)blockIdx.x * 1536);
        const float4* sp = (const float4*)so;
        ob[tid] = sp[tid];                       // 256 of 384
        if (tid < 128)
            ob[256 + tid] = sp[256 + tid];       // remaining 128
    }
}

extern "C" void kernel_launch(void* const* d_in, const int* in_sizes, int n_in,
                              void* d_out, int out_size)
{
    // metadata order: verts, vertex_normals, bary_coords, dists, zbuf, faces, pix_to_face
    const float* vertex_normals = (const float*)d_in[1];
    const float* bary           = (const float*)d_in[2];
    const float* dists          = (const float*)d_in[3];
    const float* zbuf           = (const float*)d_in[4];
    const int*   faces          = (const int*)d_in[5];
    const int*   pix_to_face    = (const int*)d_in[6];
    float*       out            = (float*)d_out;

    const int F = in_sizes[5] / 3;   // 200000
    const int threads = 256;

    // Primary: build face records (triggers dependent launch at entry).
    build_face_records<<<(F + threads - 1) / threads, threads>>>(
        vertex_normals, faces, F);

    // Secondary: PDL — launches while prepass runs; phase 2 gated by
    // cudaGridDependencySynchronize().
    cudaLaunchConfig_t cfg = {};
    cfg.gridDim  = dim3(NPIX / 512, 1, 1);
    cfg.blockDim = dim3(threads, 1, 1);
    cfg.dynamicSmemBytes = 0;
    cudaLaunchAttribute attr[1];
    attr[0].id = cudaLaunchAttributeProgrammaticStreamSerialization;
    attr[0].val.programmaticStreamSerializationAllowed = 1;
    cfg.attrs = attr;
    cfg.numAttrs = 1;
    cudaLaunchKernelEx(&cfg, normal_shader_kernel,
                       bary, dists, zbuf, pix_to_face, out);
}